// round 5
// baseline (speedup 1.0000x reference)
#include <cuda_runtime.h>
#include <cstdint>

// out[b,h,i,j] = mask[b,h,i,j] - |slope[h] * (i - j)|
// B=2, NH=16, L=2048 -> 134,217,728 fp32 = 33,554,432 float4
// slope[h] = 2^(-0.5*(h+1)) for NH=16

static constexpr int L_LOG2 = 11;            // L = 2048
static constexpr int NH_MASK = 15;           // NH = 16
static constexpr long long N_ELEM = 2LL * 16 * 2048 * 2048;
static constexpr long long N_VEC  = N_ELEM / 4;     // 33,554,432
static constexpr int THREADS = 1024;
static constexpr int VPT = 4;                // float4 per thread (64 B)
// N_VEC / (THREADS*VPT) = 33,554,432 / 4096 = 8192 exactly -> no tail

__global__ __launch_bounds__(THREADS, 2)
void alibi_kernel(const float4* __restrict__ mask, float4* __restrict__ out) {
    long long v0 = (long long)blockIdx.x * (THREADS * VPT) + threadIdx.x;

    // front-batched independent loads (MLP_p1 = 4), stride keeps 128B coalescing
    float4 m[VPT];
#pragma unroll
    for (int k = 0; k < VPT; k++)
        m[k] = __ldcs(&mask[v0 + (long long)k * THREADS]);

#pragma unroll
    for (int k = 0; k < VPT; k++) {
        long long v = v0 + (long long)k * THREADS;
        long long idx = v << 2;                          // scalar element index
        int j = (int)(idx & ((1 << L_LOG2) - 1));
        int i = (int)((idx >> L_LOG2) & ((1 << L_LOG2) - 1));
        int h = (int)((idx >> (2 * L_LOG2)) & NH_MASK);

        float slope = exp2f(-0.5f * (float)(h + 1));
        float base  = (float)(i - j);

        float4 r;
        r.x = m[k].x - fabsf(slope * (base - 0.0f));
        r.y = m[k].y - fabsf(slope * (base - 1.0f));
        r.z = m[k].z - fabsf(slope * (base - 2.0f));
        r.w = m[k].w - fabsf(slope * (base - 3.0f));
        __stwt(&out[v], r);
    }
}

extern "C" void kernel_launch(void* const* d_in, const int* in_sizes, int n_in,
                              void* d_out, int out_size) {
    const float4* mask = (const float4*)d_in[0];
    float4* out = (float4*)d_out;

    const long long blocks = N_VEC / (THREADS * VPT);   // 8192
    alibi_kernel<<<(unsigned)blocks, THREADS>>>(mask, out);
}

// round 6
// speedup vs baseline: 1.0006x; 1.0006x over previous
#include <cuda_runtime.h>
#include <cstdint>

// out[b,h,i,j] = mask[b,h,i,j] - |slope[h] * (i - j)|
// B=2, NH=16, L=2048 -> 134,217,728 fp32 = 33,554,432 float4
// slope[h] = 2^(-0.5*(h+1)) for NH=16

static constexpr int L_LOG2 = 11;            // L = 2048
static constexpr int NH_MASK = 15;           // NH = 16
static constexpr long long N_ELEM = 2LL * 16 * 2048 * 2048;
static constexpr long long N_VEC  = N_ELEM / 4;     // 33,554,432
static constexpr int THREADS = 1024;
static constexpr int VPT = 4;                // float4 per thread (64 B)
// N_VEC / (THREADS*VPT) = 33,554,432 / 4096 = 8192 exactly -> no tail

__global__ __launch_bounds__(THREADS, 2)
void alibi_kernel(const float4* __restrict__ mask, float4* __restrict__ out) {
    long long v0 = (long long)blockIdx.x * (THREADS * VPT) + threadIdx.x;

    // front-batched independent loads (MLP_p1 = 4), stride keeps 128B coalescing
    float4 m[VPT];
#pragma unroll
    for (int k = 0; k < VPT; k++)
        m[k] = __ldcs(&mask[v0 + (long long)k * THREADS]);

#pragma unroll
    for (int k = 0; k < VPT; k++) {
        long long v = v0 + (long long)k * THREADS;
        long long idx = v << 2;                          // scalar element index
        int j = (int)(idx & ((1 << L_LOG2) - 1));
        int i = (int)((idx >> L_LOG2) & ((1 << L_LOG2) - 1));
        int h = (int)((idx >> (2 * L_LOG2)) & NH_MASK);

        float slope = exp2f(-0.5f * (float)(h + 1));
        float base  = (float)(i - j);

        float4 r;
        r.x = m[k].x - fabsf(slope * (base - 0.0f));
        r.y = m[k].y - fabsf(slope * (base - 1.0f));
        r.z = m[k].z - fabsf(slope * (base - 2.0f));
        r.w = m[k].w - fabsf(slope * (base - 3.0f));
        __stwt(&out[v], r);
    }
}

extern "C" void kernel_launch(void* const* d_in, const int* in_sizes, int n_in,
                              void* d_out, int out_size) {
    const float4* mask = (const float4*)d_in[0];
    float4* out = (float4*)d_out;

    const long long blocks = N_VEC / (THREADS * VPT);   // 8192
    alibi_kernel<<<(unsigned)blocks, THREADS>>>(mask, out);
}

// round 7
// speedup vs baseline: 1.0047x; 1.0041x over previous
#include <cuda_runtime.h>
#include <cstdint>

// out[b,h,i,j] = mask[b,h,i,j] - |slope[h] * (i - j)|
// B=2, NH=16, L=2048 -> 134,217,728 fp32 = 33,554,432 float4
// slope[h] = 2^(-0.5*(h+1)) for NH=16
// All indices fit in 32 bits: N_VEC = 2^25, elem idx < 2^27, byte off < 2^29.

static constexpr int L_LOG2 = 11;                 // L = 2048
static constexpr int NH_MASK = 15;                // NH = 16
static constexpr unsigned N_ELEM_LOG2 = 27;       // 2*16*2048*2048 = 2^27
static constexpr unsigned N_VEC = 1u << (N_ELEM_LOG2 - 2);  // 33,554,432
static constexpr int THREADS = 256;
static constexpr int VPT = 8;                     // float4 per thread (128 B)
// N_VEC / (THREADS*VPT) = 16384 exactly -> no tail

__global__ __launch_bounds__(THREADS)
void alibi_kernel(const float4* __restrict__ mask, float4* __restrict__ out) {
    const unsigned v0 = blockIdx.x * (THREADS * VPT) + threadIdx.x;

    // front-batched independent loads (MLP_p1 = 8), immediate offsets off one base
    const float4* __restrict__ src = mask + v0;
    float4 m[VPT];
#pragma unroll
    for (int k = 0; k < VPT; k++)
        m[k] = __ldcs(src + k * THREADS);

    float4* __restrict__ dst = out + v0;
#pragma unroll
    for (int k = 0; k < VPT; k++) {
        unsigned v = v0 + (unsigned)(k * THREADS);
        unsigned idx = v << 2;                         // scalar element index (< 2^27)
        int j = (int)(idx & ((1u << L_LOG2) - 1u));
        int i = (int)((idx >> L_LOG2) & ((1u << L_LOG2) - 1u));
        int h = (int)((idx >> (2 * L_LOG2)) & NH_MASK);

        float slope = exp2f(-0.5f * (float)(h + 1));
        float base  = (float)(i - j);

        float4 r;
        r.x = m[k].x - fabsf(slope * (base - 0.0f));
        r.y = m[k].y - fabsf(slope * (base - 1.0f));
        r.z = m[k].z - fabsf(slope * (base - 2.0f));
        r.w = m[k].w - fabsf(slope * (base - 3.0f));
        __stcs(dst + k * THREADS, r);
    }
}

extern "C" void kernel_launch(void* const* d_in, const int* in_sizes, int n_in,
                              void* d_out, int out_size) {
    const float4* mask = (const float4*)d_in[0];
    float4* out = (float4*)d_out;

    const unsigned blocks = N_VEC / (THREADS * VPT);   // 16384
    alibi_kernel<<<blocks, THREADS>>>(mask, out);
}

// round 8
// speedup vs baseline: 1.0092x; 1.0045x over previous
#include <cuda_runtime.h>
#include <cstdint>

// out[b,h,i,j] = mask[b,h,i,j] - |slope[h] * (i - j)|
// B=2, NH=16, L=2048 -> 134,217,728 fp32 = 33,554,432 float4
// slope[h] = 2^(-0.5*(h+1)) for NH=16
// Pure HBM-streaming kernel: 512 MiB read + 512 MiB write (minimum traffic).
// Measured plateau ~86.5% of 8 TB/s across {MLP 4/8} x {occ 49-79%} — the
// 1:1 read/write turnaround ceiling of the memory path. This is the best
// measured configuration (MLP_p1=4, 256 thr, 8 CTAs/SM).

static constexpr int L_LOG2 = 11;                  // L = 2048
static constexpr int NH_MASK = 15;                 // NH = 16
static constexpr unsigned N_VEC = 1u << 25;        // 2^27 elems / 4 = 33,554,432
static constexpr int THREADS = 256;
static constexpr int VPT = 4;                      // float4 per thread (64 B)
// N_VEC / (THREADS*VPT) = 32768 exactly -> no tail

__global__ __launch_bounds__(THREADS)
void alibi_kernel(const float4* __restrict__ mask, float4* __restrict__ out) {
    const unsigned v0 = blockIdx.x * (THREADS * VPT) + threadIdx.x;

    // front-batched independent loads (MLP_p1 = 4), immediate offsets off one base
    const float4* __restrict__ src = mask + v0;
    float4 m[VPT];
#pragma unroll
    for (int k = 0; k < VPT; k++)
        m[k] = __ldcs(src + k * THREADS);

    float4* __restrict__ dst = out + v0;
#pragma unroll
    for (int k = 0; k < VPT; k++) {
        unsigned idx = (v0 + (unsigned)(k * THREADS)) << 2;   // elem index < 2^27
        int j = (int)(idx & ((1u << L_LOG2) - 1u));
        int i = (int)((idx >> L_LOG2) & ((1u << L_LOG2) - 1u));
        int h = (int)((idx >> (2 * L_LOG2)) & NH_MASK);

        float slope = exp2f(-0.5f * (float)(h + 1));
        float base  = (float)(i - j);

        float4 r;
        r.x = m[k].x - fabsf(slope * (base - 0.0f));
        r.y = m[k].y - fabsf(slope * (base - 1.0f));
        r.z = m[k].z - fabsf(slope * (base - 2.0f));
        r.w = m[k].w - fabsf(slope * (base - 3.0f));
        __stcs(dst + k * THREADS, r);
    }
}

extern "C" void kernel_launch(void* const* d_in, const int* in_sizes, int n_in,
                              void* d_out, int out_size) {
    const float4* mask = (const float4*)d_in[0];
    float4* out = (float4*)d_out;

    const unsigned blocks = N_VEC / (THREADS * VPT);   // 32768
    alibi_kernel<<<blocks, THREADS>>>(mask, out);
}

// round 9
// speedup vs baseline: 1.0107x; 1.0014x over previous
#include <cuda_runtime.h>
#include <cstdint>

// out[b,h,i,j] = mask[b,h,i,j] - |slope[h] * (i - j)|
// B=2, NH=16, L=2048 -> 134,217,728 fp32 = 33,554,432 float4
// slope[h] = 2^(-0.5*(h+1)) for NH=16
// Pure HBM-streaming kernel: 512 MiB read + 512 MiB write (compulsory minimum).
// Measured plateau ~86.5% of 8 TB/s across {MLP 4/8} x {occ 49-79%} — the
// 1:1 read/write turnaround ceiling of the memory path.
// This round: last untested grid shape (512 thr, VPT=4, full occupancy).

static constexpr int L_LOG2 = 11;                  // L = 2048
static constexpr int NH_MASK = 15;                 // NH = 16
static constexpr unsigned N_VEC = 1u << 25;        // 2^27 elems / 4 = 33,554,432
static constexpr int THREADS = 512;
static constexpr int VPT = 4;                      // float4 per thread (64 B)
// N_VEC / (THREADS*VPT) = 16384 exactly -> no tail

__global__ __launch_bounds__(THREADS)
void alibi_kernel(const float4* __restrict__ mask, float4* __restrict__ out) {
    const unsigned v0 = blockIdx.x * (THREADS * VPT) + threadIdx.x;

    // front-batched independent loads (MLP_p1 = 4), immediate offsets off one base
    const float4* __restrict__ src = mask + v0;
    float4 m[VPT];
#pragma unroll
    for (int k = 0; k < VPT; k++)
        m[k] = __ldcs(src + k * THREADS);

    float4* __restrict__ dst = out + v0;
#pragma unroll
    for (int k = 0; k < VPT; k++) {
        unsigned idx = (v0 + (unsigned)(k * THREADS)) << 2;   // elem index < 2^27
        int j = (int)(idx & ((1u << L_LOG2) - 1u));
        int i = (int)((idx >> L_LOG2) & ((1u << L_LOG2) - 1u));
        int h = (int)((idx >> (2 * L_LOG2)) & NH_MASK);

        float slope = exp2f(-0.5f * (float)(h + 1));
        float base  = (float)(i - j);

        float4 r;
        r.x = m[k].x - fabsf(slope * (base - 0.0f));
        r.y = m[k].y - fabsf(slope * (base - 1.0f));
        r.z = m[k].z - fabsf(slope * (base - 2.0f));
        r.w = m[k].w - fabsf(slope * (base - 3.0f));
        __stcs(dst + k * THREADS, r);
    }
}

extern "C" void kernel_launch(void* const* d_in, const int* in_sizes, int n_in,
                              void* d_out, int out_size) {
    const float4* mask = (const float4*)d_in[0];
    float4* out = (float4*)d_out;

    const unsigned blocks = N_VEC / (THREADS * VPT);   // 16384
    alibi_kernel<<<blocks, THREADS>>>(mask, out);
}

// round 10
// speedup vs baseline: 1.0109x; 1.0002x over previous
#include <cuda_runtime.h>
#include <cstdint>

// out[b,h,i,j] = mask[b,h,i,j] - |slope[h] * (i - j)|
// B=2, NH=16, L=2048 -> 134,217,728 fp32 = 33,554,432 float4
// slope[h] = 2^(-0.5*(h+1)) for NH=16
//
// Pure HBM-streaming kernel: 512 MiB read + 512 MiB write (compulsory minimum).
// Measured plateau: 85.6-86.7% of 8 TB/s across {MLP 1/4/8} x {256/512/1024 thr}
// x {cs/wt} x {occ 49-79%} -> 148.4-149.9 us ncu. This is the 1:1 R/W-stream
// ceiling of the LTS/HBM path (path-independent per B300 model). Final config:
// best measured point (MLP_p1=4, 256 thr, regs 32, 8 CTAs/SM, exact grid).

static constexpr int L_LOG2 = 11;                  // L = 2048
static constexpr int NH_MASK = 15;                 // NH = 16
static constexpr unsigned N_VEC = 1u << 25;        // 2^27 elems / 4
static constexpr int THREADS = 256;
static constexpr int VPT = 4;                      // float4 per thread (64 B)
// N_VEC / (THREADS*VPT) = 32768 exactly -> no tail, no bounds check

__device__ __forceinline__ float alibi_slope(int h) {
    // slope = 2^(-0.5*(h+1)).  e = (h+1)>>1 full halvings; odd (h+1) adds sqrt(1/2).
    int hp1 = h + 1;
    int e = hp1 >> 1;                                  // 0..8
    float p = __uint_as_float((unsigned)(127 - e) << 23);   // exact 2^-e
    return (hp1 & 1) ? p * 0.70710678118654752f : p;   // * sqrt(1/2) if odd
}

__global__ __launch_bounds__(THREADS)
void alibi_kernel(const float4* __restrict__ mask, float4* __restrict__ out) {
    const unsigned v0 = blockIdx.x * (THREADS * VPT) + threadIdx.x;

    // front-batched independent loads (MLP_p1 = 4), immediate offsets off one base
    const float4* __restrict__ src = mask + v0;
    float4 m[VPT];
#pragma unroll
    for (int k = 0; k < VPT; k++)
        m[k] = __ldcs(src + k * THREADS);

    float4* __restrict__ dst = out + v0;
#pragma unroll
    for (int k = 0; k < VPT; k++) {
        unsigned idx = (v0 + (unsigned)(k * THREADS)) << 2;   // elem index < 2^27
        int j = (int)(idx & ((1u << L_LOG2) - 1u));
        int i = (int)((idx >> L_LOG2) & ((1u << L_LOG2) - 1u));
        int h = (int)((idx >> (2 * L_LOG2)) & NH_MASK);

        float slope = alibi_slope(h);
        float base  = (float)(i - j);

        float4 r;
        r.x = m[k].x - fabsf(slope * (base - 0.0f));
        r.y = m[k].y - fabsf(slope * (base - 1.0f));
        r.z = m[k].z - fabsf(slope * (base - 2.0f));
        r.w = m[k].w - fabsf(slope * (base - 3.0f));
        __stcs(dst + k * THREADS, r);
    }
}

extern "C" void kernel_launch(void* const* d_in, const int* in_sizes, int n_in,
                              void* d_out, int out_size) {
    const float4* mask = (const float4*)d_in[0];
    float4* out = (float4*)d_out;

    const unsigned blocks = N_VEC / (THREADS * VPT);   // 32768
    alibi_kernel<<<blocks, THREADS>>>(mask, out);
}